// round 14
// baseline (speedup 1.0000x reference)
#include <cuda_runtime.h>
#include <cuda_bf16.h>
#include <math.h>

#define NN 4096
#define C 7
#define MAXDEG 96
#define VT (MAXDEG + 1)
#define LISTCAP 2048
#define SIG1 0.731058578630004896f   // sigmoid(1)

// ---- static device scratch (zero at load; self-cleaning across replays) ----
__device__ int    g_deg[NN];          // full degree (global atomic counters; reset by combine)
__device__ int    g_degm[NN];         // masked-neighbor count (reset by combine)
__device__ int    g_info[NN];         // label | mask<<3 | diag<<4 (overwritten each call)
__device__ float  g_endp[NN];         // exp(-preds[p, l_p])
__device__ float  g_eP[NN * C];       // exp(preds[q, i])
__device__ float  g_vtab[VT * VT];    // v(sub, inter)
__device__ int    g_nbr[NN * MAXDEG];   // all neighbors
__device__ int    g_nbrm[NN * MAXDEG];  // masked neighbors only
__device__ double g_dcc[C * C];
__device__ int    g_hi[C * C];
__device__ int    g_hs[C * C];
__device__ int    g_N[C];
__device__ float  g_T[C * C];
__device__ double g_ce;

__device__ __forceinline__ float vfun(float sub, float inter) {
    float r = (1.0f + SIG1 * sub) / (1.0f + SIG1 * inter);
    return 1.0f / (1.0f + expf(r));
}

// ---- build: upper-triangle scan (32MB), edges appended to BOTH endpoints ----
__global__ void k_build(const int* __restrict__ adj,
                        const float* __restrict__ preds,
                        const int* __restrict__ labels,
                        const int* __restrict__ mask) {
    int p = blockIdx.x, t = threadIdx.x;
    __shared__ int diag;
    __shared__ int sN[C];

    if (p == 0) {
        if (t < C) sN[t] = 0;
        __syncthreads();
        int c0=0,c1=0,c2=0,c3=0,c4=0,c5=0,c6=0;
        for (int i = t; i < NN; i += blockDim.x) {
            if (mask[i]) {
                int l = labels[i];
                c0 += (l==0); c1 += (l==1); c2 += (l==2); c3 += (l==3);
                c4 += (l==4); c5 += (l==5); c6 += (l==6);
            }
        }
        if (c0) atomicAdd(&sN[0], c0);
        if (c1) atomicAdd(&sN[1], c1);
        if (c2) atomicAdd(&sN[2], c2);
        if (c3) atomicAdd(&sN[3], c3);
        if (c4) atomicAdd(&sN[4], c4);
        if (c5) atomicAdd(&sN[5], c5);
        if (c6) atomicAdd(&sN[6], c6);
        for (int i = t; i < VT * VT; i += blockDim.x)
            g_vtab[i] = vfun((float)(i / VT), (float)(i % VT));
        __syncthreads();
        if (t < C) g_N[t] = sN[t];
    }

    if (t == 0) diag = 0;
    __syncthreads();
    int maskp = mask[p];
    const int4* row4 = (const int4*)(adj + (size_t)p * NN);
    int qb0 = p >> 2;
    for (int qb = qb0 + t; qb < NN / 4; qb += blockDim.x) {
        int4 v = row4[qb];
        if ((v.x | v.y | v.z | v.w) == 0) continue;     // ~98% of quads
        int base = qb * 4;
        #pragma unroll
        for (int e = 0; e < 4; e++) {
            int bit = (e == 0) ? v.x : (e == 1) ? v.y : (e == 2) ? v.z : v.w;
            int col = base + e;
            if (!bit || col < p) continue;
            if (col == p) {                              // self-loop: one entry
                diag = 1;
                int s = atomicAdd(&g_deg[p], 1);
                if (s < MAXDEG) g_nbr[p * MAXDEG + s] = p;
                if (maskp) {
                    int sm = atomicAdd(&g_degm[p], 1);
                    if (sm < MAXDEG) g_nbrm[p * MAXDEG + sm] = p;
                }
            } else {                                     // edge p<col: both directions
                int mq = mask[col];
                int s1 = atomicAdd(&g_deg[p], 1);
                if (s1 < MAXDEG) g_nbr[p * MAXDEG + s1] = col;
                int s2 = atomicAdd(&g_deg[col], 1);
                if (s2 < MAXDEG) g_nbr[col * MAXDEG + s2] = p;
                if (mq) {
                    int sm = atomicAdd(&g_degm[p], 1);
                    if (sm < MAXDEG) g_nbrm[p * MAXDEG + sm] = col;
                }
                if (maskp) {
                    int sm = atomicAdd(&g_degm[col], 1);
                    if (sm < MAXDEG) g_nbrm[col * MAXDEG + sm] = p;
                }
            }
        }
    }
    __syncthreads();
    if (t == 0) {
        int lp = labels[p];
        g_info[p] = lp | (maskp ? 8 : 0) | (diag ? 16 : 0);
        // deg-independent per-node stats
        const float* r = preds + p * C;
        float v0 = r[0], v1 = r[1], v2 = r[2], v3 = r[3], v4 = r[4], v5 = r[5], v6 = r[6];
        float rl = r[lp];
        float mx = fmaxf(fmaxf(fmaxf(v0, v1), fmaxf(v2, v3)), fmaxf(fmaxf(v4, v5), v6));
        float e0 = expf(v0-mx), e1 = expf(v1-mx), e2 = expf(v2-mx), e3 = expf(v3-mx);
        float e4 = expf(v4-mx), e5 = expf(v5-mx), e6 = expf(v6-mx);
        float se = e0+e1+e2+e3+e4+e5+e6;
        atomicAdd(&g_ce, (double)(rl - (mx + logf(se))));
        float emx = expf(mx);
        float p0 = e0*emx, p1 = e1*emx, p2 = e2*emx, p3 = e3*emx,
              p4 = e4*emx, p5 = e5*emx, p6 = e6*emx;
        float* eP = g_eP + p * C;
        eP[0]=p0; eP[1]=p1; eP[2]=p2; eP[3]=p3; eP[4]=p4; eP[5]=p5; eP[6]=p6;
        g_endp[p] = expf(-rl);
        if (maskp) {
            atomicAdd(&g_T[0*C+lp], p0);
            atomicAdd(&g_T[1*C+lp], p1);
            atomicAdd(&g_T[2*C+lp], p2);
            atomicAdd(&g_T[3*C+lp], p3);
            atomicAdd(&g_T[4*C+lp], p4);
            atomicAdd(&g_T[5*C+lp], p5);
            atomicAdd(&g_T[6*C+lp], p6);
        }
    }
}

// ---- persistent wedge: 2 nodes per block, counters zeroed once, touched rezero ----
__global__ void __launch_bounds__(128)
k_wedge() {
    __shared__ unsigned cnt[NN / 2];   // two 16b lanes/word: bits0-14 inter, bit15 nbr mark
    __shared__ unsigned short lst[LISTCAP];
    __shared__ int   sk[MAXDEG];
    __shared__ int   sdm[MAXDEG];
    __shared__ int   nlist;
    __shared__ float sdcc[C];
    __shared__ int   shi[C], szc[C];

    int t = threadIdx.x;
    uint4* c4 = (uint4*)cnt;
    #pragma unroll
    for (int i = t; i < NN / 8; i += 128) c4[i] = make_uint4(0u, 0u, 0u, 0u);
    __syncthreads();

    int wid = t >> 5, lane = t & 31;

    #pragma unroll
    for (int pp = 0; pp < 2; pp++) {
        int p = blockIdx.x * 2 + pp;
        int infop = g_info[p];
        int degp  = g_deg[p];
        if (!(infop & 8) || degp == 0) continue;
        int dl = (degp < MAXDEG) ? degp : MAXDEG;
        int lp = infop & 7;

        if (t < C) { sdcc[t] = 0.0f; shi[t] = 0; szc[t] = 0; }
        if (t == 0) nlist = 0;
        if (t < dl) {
            int k = g_nbr[p * MAXDEG + t];
            sk[t]  = k;
            int dm = g_degm[k];
            sdm[t] = (dm < MAXDEG) ? dm : MAXDEG;
        }
        __syncthreads();

        // phase 1: scatter wedge counts to MASKED q only
        for (int a = wid; a < dl; a += 4) {
            int k = sk[a], dmk = sdm[a];
            const int* nk = g_nbrm + k * MAXDEG;
            for (int b = lane; b < dmk; b += 32) {
                int q = nk[b];
                int sh = (q & 1) * 16;
                unsigned old = atomicAdd(&cnt[q >> 1], 1u << sh);
                if (((old >> sh) & 0xFFFFu) == 0u) {
                    int s = atomicAdd(&nlist, 1);
                    if (s < LISTCAP) lst[s] = (unsigned short)q;
                }
            }
        }
        {   // neighbor marks: masked neighbors of p
            int dmp = g_degm[p];
            if (dmp > MAXDEG) dmp = MAXDEG;
            const int* npm = g_nbrm + p * MAXDEG;
            for (int a = t; a < dmp; a += 128) {
                int q = npm[a];
                int sh = (q & 1) * 16;
                unsigned old = atomicOr(&cnt[q >> 1], 0x8000u << sh);
                if (((old >> sh) & 0xFFFFu) == 0u) {
                    int s = atomicAdd(&nlist, 1);
                    if (s < LISTCAP) lst[s] = (unsigned short)q;
                }
            }
        }
        __syncthreads();

        // phase 2: touched entries only; clear own lane after reading
        float endp = g_endp[p];
        float v0   = g_vtab[dl * VT];                   // v(degp, 0)
        int nl = nlist;
        if (nl <= LISTCAP) {
            for (int ii = t; ii < nl; ii += 128) {
                int q = lst[ii];
                int sh = (q & 1) * 16;
                unsigned c = (cnt[q >> 1] >> sh) & 0xFFFFu;
                atomicAnd(&cnt[q >> 1], ~(0xFFFFu << sh));   // touched-only rezero
                int info  = g_info[q];
                int inter = (int)(c & 0x7FFFu);
                int corr  = (int)(c >> 15) & (~(info >> 4) & 1);
                if ((inter | corr) == 0) continue;           // marked diag-q only
                int lq = info & 7;
                int sub = degp - inter - corr;
                if (inter > 0) shi[lq] = 1;
                if (sub == 0)  atomicAdd(&szc[lq], 1);
                if (lq != lp) {
                    float d = endp * g_eP[q * C + lp] *
                              (g_vtab[sub * VT + inter] - v0);
                    atomicAdd(&sdcc[lq], d);
                }
            }
        } else {                     // overflow fallback: full packed scan + full rezero
            for (int i = t; i < NN / 8; i += 128) {
                uint4 w4 = c4[i];
                if ((w4.x | w4.y | w4.z | w4.w) == 0u) continue;
                c4[i] = make_uint4(0u, 0u, 0u, 0u);
                #pragma unroll
                for (int cc = 0; cc < 4; cc++) {
                    unsigned word = (cc==0)?w4.x:(cc==1)?w4.y:(cc==2)?w4.z:w4.w;
                    if (!word) continue;
                    #pragma unroll
                    for (int h = 0; h < 2; h++) {
                        unsigned v = (word >> (h * 16)) & 0xFFFFu;
                        if (!v) continue;
                        int q = (i * 4 + cc) * 2 + h;
                        int info  = g_info[q];
                        int inter = (int)(v & 0x7FFFu);
                        int corr  = (int)(v >> 15) & (~(info >> 4) & 1);
                        if ((inter | corr) == 0) continue;
                        int lq = info & 7;
                        int sub = degp - inter - corr;
                        if (inter > 0) shi[lq] = 1;
                        if (sub == 0)  atomicAdd(&szc[lq], 1);
                        if (lq != lp) {
                            float d = endp * g_eP[q * C + lp] *
                                      (g_vtab[sub * VT + inter] - v0);
                            atomicAdd(&sdcc[lq], d);
                        }
                    }
                }
            }
        }
        __syncthreads();
        if (t < C) {
            if (sdcc[t] != 0.0f) atomicAdd(&g_dcc[lp * C + t], (double)sdcc[t]);
            if (shi[t]) g_hi[lp * C + t] = 1;
            if (szc[t] < g_N[t]) g_hs[lp * C + t] = 1;    // exists masked label-t q with sub>0
        }
        __syncthreads();   // protect smem before next p
    }
}

// ---- combine: U reduction + 49 class pairs; resets all counters for replay ----
__global__ void k_combine(float* __restrict__ out) {
    __shared__ float sU[C];
    int t = threadIdx.x;
    if (t < C) sU[t] = 0.0f;
    __syncthreads();

    // U[i] = sum_{p masked, l=i} endp[p] * v(deg[p], 0)   (deg now final)
    float u0=0,u1=0,u2=0,u3=0,u4=0,u5=0,u6=0;
    for (int p = t; p < NN; p += blockDim.x) {
        int info = g_info[p];
        if (info & 8) {
            int d = g_deg[p];
            if (d > MAXDEG) d = MAXDEG;
            float u = g_endp[p] * g_vtab[d * VT];
            int l = info & 7;
            u0 += (l==0)?u:0.0f; u1 += (l==1)?u:0.0f; u2 += (l==2)?u:0.0f;
            u3 += (l==3)?u:0.0f; u4 += (l==4)?u:0.0f; u5 += (l==5)?u:0.0f;
            u6 += (l==6)?u:0.0f;
        }
        g_deg[p] = 0;                 // reset for next replay
        g_degm[p] = 0;
    }
    if (u0) atomicAdd(&sU[0], u0);
    if (u1) atomicAdd(&sU[1], u1);
    if (u2) atomicAdd(&sU[2], u2);
    if (u3) atomicAdd(&sU[3], u3);
    if (u4) atomicAdd(&sU[4], u4);
    if (u5) atomicAdd(&sU[5], u5);
    if (u6) atomicAdd(&sU[6], u6);
    __syncthreads();

    if (t == 0) {
        double tot = 0.0;
        for (int i = 0; i < C; i++) {
            double inv_i = (g_N[i] > 0) ? 1.0 / (double)g_N[i] : 0.0;
            for (int j = 0; j < C; j++) {
                if (i == j) continue;
                if (g_hs[i * C + j] && g_hi[i * C + j]) {
                    double inv_j = (g_N[j] > 0) ? 1.0 / (double)g_N[j] : 0.0;
                    tot += inv_i * inv_j *
                           ((double)sU[i] * (double)g_T[i * C + j] + g_dcc[i * C + j]);
                }
            }
        }
        out[0] = (float)(-(g_ce / (double)NN) + 0.001 * tot);
        g_ce = 0.0;
    }
    __syncthreads();
    if (t < C * C) { g_dcc[t] = 0.0; g_hi[t] = 0; g_hs[t] = 0; g_T[t] = 0.0f; }
}

extern "C" void kernel_launch(void* const* d_in, const int* in_sizes, int n_in,
                              void* d_out, int out_size) {
    const float* preds  = (const float*)d_in[0];
    const int*   labels = (const int*)d_in[1];
    const int*   mask   = (const int*)d_in[2];
    const int*   adj    = (const int*)d_in[3];
    float* out = (float*)d_out;

    k_build  <<<NN, 256>>>(adj, preds, labels, mask);
    k_wedge  <<<NN / 2, 128>>>();
    k_combine<<<1, 256>>>(out);
}

// round 15
// speedup vs baseline: 1.7397x; 1.7397x over previous
#include <cuda_runtime.h>
#include <cuda_bf16.h>
#include <math.h>

#define NN 4096
#define C 7
#define MAXDEG 96
#define VT (MAXDEG + 1)
#define LISTCAP 2048
#define NBLK 2048
#define SIG1 0.731058578630004896f   // sigmoid(1)

// ---- static device scratch (zero at load; self-cleaning across replays) ----
__device__ int    g_deg[NN];          // full degree
__device__ int    g_degm[NN];         // masked-neighbor count
__device__ int    g_info[NN];         // label | mask<<3 | diag<<4
__device__ float  g_endp[NN];         // exp(-preds[p, l_p])
__device__ float  g_eP[NN * C];       // exp(preds[q, i])
__device__ float  g_vtab[VT * VT];    // v(sub, inter)
__device__ int    g_nbr[NN * MAXDEG];   // all neighbors
__device__ int    g_nbrm[NN * MAXDEG];  // masked neighbors only
__device__ int    g_active[NN];       // compacted list of active p
__device__ int    g_nactive;          // count (reset by k_combine)
__device__ double g_dcc[C * C];
__device__ int    g_hi[C * C];
__device__ int    g_hs[C * C];
__device__ int    g_N[C];
__device__ float  g_T[C * C];
__device__ float  g_U[C];
__device__ double g_ce;

__device__ __forceinline__ float vfun(float sub, float inter) {
    float r = (1.0f + SIG1 * sub) / (1.0f + SIG1 * inter);
    return 1.0f / (1.0f + expf(r));
}

// ---- build: lists (full + masked) + per-node precompute; block 0: g_N + vtab ----
__global__ void k_build(const int* __restrict__ adj,
                        const float* __restrict__ preds,
                        const int* __restrict__ labels,
                        const int* __restrict__ mask) {
    int p = blockIdx.x, t = threadIdx.x;
    __shared__ int cnt, cntm, diag;
    __shared__ int sN[C];

    if (p == 0) {
        if (t < C) sN[t] = 0;
        __syncthreads();
        int c0=0,c1=0,c2=0,c3=0,c4=0,c5=0,c6=0;
        for (int i = t; i < NN; i += blockDim.x) {
            if (mask[i]) {
                int l = labels[i];
                c0 += (l==0); c1 += (l==1); c2 += (l==2); c3 += (l==3);
                c4 += (l==4); c5 += (l==5); c6 += (l==6);
            }
        }
        if (c0) atomicAdd(&sN[0], c0);
        if (c1) atomicAdd(&sN[1], c1);
        if (c2) atomicAdd(&sN[2], c2);
        if (c3) atomicAdd(&sN[3], c3);
        if (c4) atomicAdd(&sN[4], c4);
        if (c5) atomicAdd(&sN[5], c5);
        if (c6) atomicAdd(&sN[6], c6);
        for (int i = t; i < VT * VT; i += blockDim.x)
            g_vtab[i] = vfun((float)(i / VT), (float)(i % VT));
        __syncthreads();
        if (t < C) g_N[t] = sN[t];
    }

    if (t == 0) { cnt = 0; cntm = 0; diag = 0; }
    __syncthreads();
    const int4* row = (const int4*)(adj + (size_t)p * NN);
    int4 v[4];
    #pragma unroll
    for (int j = 0; j < 4; j++) v[j] = row[t + j * 256];
    #pragma unroll
    for (int j = 0; j < 4; j++) {
        if ((v[j].x | v[j].y | v[j].z | v[j].w) == 0) continue;   // ~98% of quads
        int q = (t + j * 256) * 4;
        #pragma unroll
        for (int e = 0; e < 4; e++) {
            int bit = (e == 0) ? v[j].x : (e == 1) ? v[j].y : (e == 2) ? v[j].z : v[j].w;
            if (bit) {
                int qq = q + e;
                int s = atomicAdd(&cnt, 1);
                if (s < MAXDEG) g_nbr[p * MAXDEG + s] = qq;
                if (mask[qq]) {
                    int sm = atomicAdd(&cntm, 1);
                    if (sm < MAXDEG) g_nbrm[p * MAXDEG + sm] = qq;
                }
                if (qq == p) diag = 1;
            }
        }
    }
    __syncthreads();
    if (t == 0) {
        int degp = (cnt < MAXDEG) ? cnt : MAXDEG;
        g_deg[p]  = degp;
        g_degm[p] = (cntm < MAXDEG) ? cntm : MAXDEG;
        int mp = mask[p];
        int lp = labels[p];
        g_info[p] = lp | (mp ? 8 : 0) | (diag ? 16 : 0);
        if (mp && degp > 0) {
            int s = atomicAdd(&g_nactive, 1);
            g_active[s] = p;
        }

        const float* r = preds + p * C;
        float v0 = r[0], v1 = r[1], v2 = r[2], v3 = r[3], v4 = r[4], v5 = r[5], v6 = r[6];
        float rl = r[lp];
        float mx = fmaxf(fmaxf(fmaxf(v0, v1), fmaxf(v2, v3)), fmaxf(fmaxf(v4, v5), v6));
        float e0 = expf(v0-mx), e1 = expf(v1-mx), e2 = expf(v2-mx), e3 = expf(v3-mx);
        float e4 = expf(v4-mx), e5 = expf(v5-mx), e6 = expf(v6-mx);
        float se = e0+e1+e2+e3+e4+e5+e6;
        atomicAdd(&g_ce, (double)(rl - (mx + logf(se))));
        float emx = expf(mx);
        float p0 = e0*emx, p1 = e1*emx, p2 = e2*emx, p3 = e3*emx,
              p4 = e4*emx, p5 = e5*emx, p6 = e6*emx;
        float* eP = g_eP + p * C;
        eP[0]=p0; eP[1]=p1; eP[2]=p2; eP[3]=p3; eP[4]=p4; eP[5]=p5; eP[6]=p6;
        float endp = expf(-rl);
        g_endp[p] = endp;
        if (mp) {
            atomicAdd(&g_T[0*C+lp], p0);
            atomicAdd(&g_T[1*C+lp], p1);
            atomicAdd(&g_T[2*C+lp], p2);
            atomicAdd(&g_T[3*C+lp], p3);
            atomicAdd(&g_T[4*C+lp], p4);
            atomicAdd(&g_T[5*C+lp], p5);
            atomicAdd(&g_T[6*C+lp], p6);
            atomicAdd(&g_U[lp], endp * vfun((float)degp, 0.0f));
        }
    }
}

// ---- persistent wedge: active list (~1 node/block), counters zeroed once ----
__global__ void __launch_bounds__(128)
k_wedge() {
    __shared__ unsigned cnt[NN / 2];   // two 16b lanes/word: bits0-14 inter, bit15 nbr mark
    __shared__ unsigned short lst[LISTCAP];
    __shared__ int   sk[MAXDEG];
    __shared__ int   sdm[MAXDEG];
    __shared__ int   nlist;
    __shared__ float sdcc[C];
    __shared__ int   shi[C], szc[C];

    int t = threadIdx.x;
    uint4* c4 = (uint4*)cnt;
    #pragma unroll
    for (int i = t; i < NN / 8; i += 128) c4[i] = make_uint4(0u, 0u, 0u, 0u);

    int nact = g_nactive;
    int wid = t >> 5, lane = t & 31;

    for (int it = blockIdx.x; it < nact; it += NBLK) {
        int p = g_active[it];
        int degp = g_deg[p];
        int lp   = g_info[p] & 7;

        if (t < C) { sdcc[t] = 0.0f; shi[t] = 0; szc[t] = 0; }
        if (t == 0) nlist = 0;
        // prefetch neighbor ids + masked degrees (parallel, high MLP)
        if (t < degp) {
            int k = g_nbr[p * MAXDEG + t];
            sk[t]  = k;
            sdm[t] = g_degm[k];
        }
        __syncthreads();

        // phase 1: scatter wedge counts to MASKED q only
        for (int a = wid; a < degp; a += 4) {
            int k = sk[a], dmk = sdm[a];
            const int* nk = g_nbrm + k * MAXDEG;
            for (int b = lane; b < dmk; b += 32) {
                int q = nk[b];
                int sh = (q & 1) * 16;
                unsigned old = atomicAdd(&cnt[q >> 1], 1u << sh);
                if (((old >> sh) & 0xFFFFu) == 0u) {
                    int s = atomicAdd(&nlist, 1);
                    if (s < LISTCAP) lst[s] = (unsigned short)q;
                }
            }
        }
        {   // neighbor marks: masked neighbors of p
            int dmp = g_degm[p];
            const int* npm = g_nbrm + p * MAXDEG;
            for (int a = t; a < dmp; a += 128) {
                int q = npm[a];
                int sh = (q & 1) * 16;
                unsigned old = atomicOr(&cnt[q >> 1], 0x8000u << sh);
                if (((old >> sh) & 0xFFFFu) == 0u) {
                    int s = atomicAdd(&nlist, 1);
                    if (s < LISTCAP) lst[s] = (unsigned short)q;
                }
            }
        }
        __syncthreads();

        // phase 2: touched entries only; clear own lane after processing
        float endp = g_endp[p];
        float v0   = g_vtab[degp * VT];                   // v(degp, 0)
        int nl = nlist;
        if (nl <= LISTCAP) {
            for (int ii = t; ii < nl; ii += 128) {
                int q = lst[ii];
                int sh = (q & 1) * 16;
                unsigned c = (cnt[q >> 1] >> sh) & 0xFFFFu;
                atomicAnd(&cnt[q >> 1], ~(0xFFFFu << sh));   // touched-only rezero
                int info  = g_info[q];
                int inter = (int)(c & 0x7FFFu);
                int corr  = (int)(c >> 15) & (~(info >> 4) & 1);
                if ((inter | corr) == 0) continue;           // marked diag-q only
                int lq = info & 7;
                int sub = degp - inter - corr;
                if (inter > 0) shi[lq] = 1;
                if (sub == 0)  atomicAdd(&szc[lq], 1);
                if (lq != lp) {
                    float d = endp * g_eP[q * C + lp] *
                              (g_vtab[sub * VT + inter] - v0);
                    atomicAdd(&sdcc[lq], d);
                }
            }
        } else {                     // overflow fallback: full packed scan + full rezero
            for (int i = t; i < NN / 8; i += 128) {
                uint4 w4 = c4[i];
                if ((w4.x | w4.y | w4.z | w4.w) == 0u) continue;
                c4[i] = make_uint4(0u, 0u, 0u, 0u);
                #pragma unroll
                for (int cc = 0; cc < 4; cc++) {
                    unsigned word = (cc==0)?w4.x:(cc==1)?w4.y:(cc==2)?w4.z:w4.w;
                    if (!word) continue;
                    #pragma unroll
                    for (int h = 0; h < 2; h++) {
                        unsigned v = (word >> (h * 16)) & 0xFFFFu;
                        if (!v) continue;
                        int q = (i * 4 + cc) * 2 + h;
                        int info  = g_info[q];
                        int inter = (int)(v & 0x7FFFu);
                        int corr  = (int)(v >> 15) & (~(info >> 4) & 1);
                        if ((inter | corr) == 0) continue;
                        int lq = info & 7;
                        int sub = degp - inter - corr;
                        if (inter > 0) shi[lq] = 1;
                        if (sub == 0)  atomicAdd(&szc[lq], 1);
                        if (lq != lp) {
                            float d = endp * g_eP[q * C + lp] *
                                      (g_vtab[sub * VT + inter] - v0);
                            atomicAdd(&sdcc[lq], d);
                        }
                    }
                }
            }
        }
        __syncthreads();
        if (t < C) {
            if (sdcc[t] != 0.0f) atomicAdd(&g_dcc[lp * C + t], (double)sdcc[t]);
            if (shi[t]) g_hi[lp * C + t] = 1;
            if (szc[t] < g_N[t]) g_hs[lp * C + t] = 1;    // exists masked label-t q with sub>0
        }
        __syncthreads();   // protect smem state before next iteration
    }
}

// ---- combine: 49 class pairs; then reset accumulators for next replay ----
__global__ void k_combine(float* __restrict__ out) {
    int t = threadIdx.x;
    if (t == 0) {
        double tot = 0.0;
        for (int i = 0; i < C; i++) {
            double inv_i = (g_N[i] > 0) ? 1.0 / (double)g_N[i] : 0.0;
            for (int j = 0; j < C; j++) {
                if (i == j) continue;
                if (g_hs[i * C + j] && g_hi[i * C + j]) {
                    double inv_j = (g_N[j] > 0) ? 1.0 / (double)g_N[j] : 0.0;
                    tot += inv_i * inv_j *
                           ((double)g_U[i] * (double)g_T[i * C + j] + g_dcc[i * C + j]);
                }
            }
        }
        out[0] = (float)(-(g_ce / (double)NN) + 0.001 * tot);
        g_ce = 0.0;
        g_nactive = 0;
    }
    __syncthreads();
    if (t < C * C) { g_dcc[t] = 0.0; g_hi[t] = 0; g_hs[t] = 0; g_T[t] = 0.0f; }
    if (t < C)     g_U[t] = 0.0f;
}

extern "C" void kernel_launch(void* const* d_in, const int* in_sizes, int n_in,
                              void* d_out, int out_size) {
    const float* preds  = (const float*)d_in[0];
    const int*   labels = (const int*)d_in[1];
    const int*   mask   = (const int*)d_in[2];
    const int*   adj    = (const int*)d_in[3];
    float* out = (float*)d_out;

    k_build  <<<NN, 256>>>(adj, preds, labels, mask);
    k_wedge  <<<NBLK, 128>>>();
    k_combine<<<1, 64>>>(out);
}